// round 17
// baseline (speedup 1.0000x reference)
#include <cuda_runtime.h>
#include <math.h>

#define BB 16
#define NAT 256
#define KNN 24
#define FF 128
#define LL 4
#define EPSC 0.01f
#define NNODE (BB*NAT)
#define NEDGE (NNODE*KNN)
#define NPAIR ((KNN*(KNN-1))/2)   // 276 pairs j<k

// ---------------- scratch (device globals; no allocation allowed) ----------------
__device__ float g_x[NNODE*3];
__device__ int   g_idx[NEDGE];
__device__ float g_h[NNODE*FF];
__device__ float g_y[2*NNODE*FF];    // ping-pong per-node W1 transform
__device__ float g_de[NNODE];        // per-node dot(h, act_we)
__device__ float g_dp[NNODE];        // per-node dot(h, actpos_we)
__device__ unsigned char g_maskp[NNODE*NPAIR];  // packed j<k triplet mask
__device__ uchar2 g_pairs[NPAIR];    // (j,k) with j<k
__device__ float g_xcart[NNODE*3];
__device__ float g_strain[BB*6];   // symmetric 3x3 packed: 00,01,02,11,12,22
__device__ float g_tri[BB*6];
__device__ float g_cell[BB*9];     // geo_cell (row-major)
__device__ float g_rho[BB*9];      // action_rho

__constant__ int c_pc[6] = {0,0,0,1,1,2};
__constant__ int c_pd[6] = {0,1,2,1,2,2};

// fast silu / tanh via MUFU (few-ulp error; tanh saturates correctly at +/-inf)
__device__ __forceinline__ float siluf(float a) {
    return __fdividef(a, 1.f + __expf(-a));
}
__device__ __forceinline__ float tanhfast(float x) {
    return 1.f - __fdividef(2.f, __expf(2.f*x) + 1.f);
}

// 128x128 GEMM on TWO input vectors sharing weight loads (see R15).
// red MUST be 16-byte aligned (float4 stores).
__device__ __forceinline__ void gemm128x2(
    const float* __restrict__ W, const float* s0, const float* s1,
    float* red, int t, float* o0, float* o1)
{
    int lane = t & 31, w = t >> 5;
    __syncthreads();
    float4 a0 = make_float4(0.f,0.f,0.f,0.f);
    float4 a1 = make_float4(0.f,0.f,0.f,0.f);
    #pragma unroll 8
    for (int f = 0; f < 32; f++) {
        float h0 = s0[32*w + f];
        float h1 = s1[32*w + f];
        float4 wv = ((const float4*)(W + (32*w + f)*FF))[lane];
        a0.x += h0*wv.x; a0.y += h0*wv.y; a0.z += h0*wv.z; a0.w += h0*wv.w;
        a1.x += h1*wv.x; a1.y += h1*wv.y; a1.z += h1*wv.z; a1.w += h1*wv.w;
    }
    ((float4*)(red + w*FF))[lane] = a0;
    ((float4*)(red + (4+w)*FF))[lane] = a1;
    __syncthreads();
    *o0 = red[0*FF + t] + red[1*FF + t] + red[2*FF + t] + red[3*FF + t];
    *o1 = red[4*FF + t] + red[5*FF + t] + red[6*FF + t] + red[7*FF + t];
}

// ---------------- init: x = mod(x,1), cells = I, accumulators = 0, traj = 0, pair LUT ------
__global__ void k_init(const float* __restrict__ x_in, float* __restrict__ out) {
    int i = blockIdx.x * blockDim.x + threadIdx.x;
    if (i < NNODE*3) { float v = x_in[i]; g_x[i] = v - floorf(v); out[i] = 0.f; }
    if (i < BB*9) {
        float id = ((i % 9) % 4 == 0) ? 1.f : 0.f;
        g_cell[i] = id; g_rho[i] = id;
    }
    if (i < BB*6) { g_strain[i] = 0.f; g_tri[i] = 0.f; }
    if (i < NPAIR) {
        int r = i, jj = 0;
        while (r >= KNN-1-jj) { r -= KNN-1-jj; jj++; }
        g_pairs[i] = make_uchar2((unsigned char)jj, (unsigned char)(jj+1+r));
    }
}

// ---------------- fused kNN + initial edge u + triplet mask (one block per node) ----------
__global__ void __launch_bounds__(256) k_knnGeo() {
    int b = blockIdx.x >> 8;
    int i = blockIdx.x & 255;
    __shared__ __align__(16) float sx[NAT*3];
    __shared__ __align__(16) unsigned long long skey[NAT];
    __shared__ int sidx[KNN];
    __shared__ float su[KNN*3];
    int t = threadIdx.x;
    for (int q = t; q < NAT*3; q += 256) sx[q] = g_x[b*NAT*3 + q];
    __syncthreads();
    float xi0 = sx[i*3+0], xi1 = sx[i*3+1], xi2 = sx[i*3+2];
    float d0 = sx[t*3+0] - xi0; d0 -= rintf(d0);
    float d1 = sx[t*3+1] - xi1; d1 -= rintf(d1);
    float d2 = sx[t*3+2] - xi2; d2 -= rintf(d2);
    float d = sqrtf(d0*d0 + d1*d1 + d2*d2);
    if (t == i) d += 1e6f;
    unsigned long long kt = ((unsigned long long)__float_as_uint(d) << 32) | (unsigned)t;
    skey[t] = kt;
    __syncthreads();
    int rank = 0;
    const ulonglong2* s2 = (const ulonglong2*)skey;
    #pragma unroll 8
    for (int q = 0; q < NAT/2; q++) {
        ulonglong2 v = s2[q];
        rank += (v.x < kt);
        rank += (v.y < kt);
    }
    int node = b*NAT + i;
    if (rank < KNN) { g_idx[node*KNN + rank] = t; sidx[rank] = t; }
    __syncthreads();

    // initial edge unit vectors (geo_cell = I at this point; same expression as k_edges)
    if (t < KNN) {
        int j = sidx[t];
        const float* C = g_cell + b*9;
        float f0 = sx[j*3+0] - xi0; f0 -= rintf(f0);
        float f1 = sx[j*3+1] - xi1; f1 -= rintf(f1);
        float f2 = sx[j*3+2] - xi2; f2 -= rintf(f2);
        float v0 = f0*C[0] + f1*C[3] + f2*C[6];
        float v1 = f0*C[1] + f1*C[4] + f2*C[7];
        float v2 = f0*C[2] + f1*C[5] + f2*C[8];
        float dd = sqrtf(v0*v0 + v1*v1 + v2*v2);
        float inv = 1.f / (dd + 1e-12f);
        su[t*3+0] = v0*inv; su[t*3+1] = v1*inv; su[t*3+2] = v2*inv;
    }
    __syncthreads();

    // packed triplet mask over j<k pairs
    for (int q = t; q < NPAIR; q += 256) {
        uchar2 pr = g_pairs[q];
        const float* a = su + pr.x*3;
        const float* c = su + pr.y*3;
        float c0 = a[1]*c[2] - a[2]*c[1];
        float c1 = a[2]*c[0] - a[0]*c[2];
        float c2 = a[0]*c[1] - a[1]*c[0];
        g_maskp[node*NPAIR + q] = (sqrtf(c0*c0 + c1*c1 + c2*c2) > 1e-3f) ? 1 : 0;
    }
}

// ---------------- first lin1 (2 nodes/block): h = emb[z]; y = h @ W1[:128,:] + b1 ----------
__global__ void __launch_bounds__(128) k_lin1n(
    const float* __restrict__ W1, const float* __restrict__ b1,
    const float* __restrict__ emb, const int* __restrict__ z)
{
    int n0 = blockIdx.x * 2;
    int t = threadIdx.x;
    __shared__ __align__(16) float sh0[FF], sh1[FF];
    __shared__ __align__(16) float red[8*FF];
    float h0 = emb[z[n0]*FF + t];
    float h1 = emb[z[n0+1]*FF + t];
    g_h[n0*FF + t] = h0;
    g_h[(n0+1)*FF + t] = h1;
    sh0[t] = h0; sh1[t] = h1;
    float a0, a1;
    gemm128x2(W1, sh0, sh1, red, t, &a0, &a1);
    float bg = b1[t];
    g_y[n0*FF + t] = a0 + bg;
    g_y[(n0+1)*FF + t] = a1 + bg;
}

// ---------------- fused MPNN layer (2 nodes/block): dist -> aggr -> lin2 -> lin1(next) -----
__global__ void __launch_bounds__(128) k_fusedL(
    const float* __restrict__ wl_row,
    const float* __restrict__ W2, const float* __restrict__ b2,
    const float* __restrict__ W1n, const float* __restrict__ b1n,
    const float* __restrict__ awe, const float* __restrict__ awp, int p)
{
    int n0 = blockIdx.x * 2;
    int b = n0 >> 8;
    int t = threadIdx.x;

    __shared__ __align__(16) float red[8*FF];
    __shared__ __align__(16) float shm0[FF], shm1[FF];
    __shared__ __align__(16) float shh0[FF], shh1[FF];
    __shared__ float sdist[2*KNN];
    __shared__ int   sj[2*KNN];
    __shared__ float snx[6];
    __shared__ float scell[9];
    __shared__ float swe[8], swp[8];

    if (t < 2*KNN) sj[t] = g_idx[n0*KNN + t];
    if (t >= 64 && t < 70) snx[t-64] = g_x[n0*3 + (t-64)];
    if (t >= 96 && t < 105) scell[t-96] = g_cell[b*9 + (t-96)];
    __syncthreads();

    // on-the-fly edge distances (same expression as the old k_edges kernel)
    if (t < 2*KNN) {
        int j = sj[t];
        const float* xb = g_x + b*NAT*3;
        int m = (t >= KNN) ? 1 : 0;
        float f0 = xb[j*3+0] - snx[m*3+0]; f0 -= rintf(f0);
        float f1 = xb[j*3+1] - snx[m*3+1]; f1 -= rintf(f1);
        float f2 = xb[j*3+2] - snx[m*3+2]; f2 -= rintf(f2);
        float v0 = f0*scell[0] + f1*scell[3] + f2*scell[6];
        float v1 = f0*scell[1] + f1*scell[4] + f2*scell[7];
        float v2 = f0*scell[2] + f1*scell[5] + f2*scell[8];
        sdist[t] = sqrtf(v0*v0 + v1*v1 + v2*v2);
    }
    __syncthreads();

    // aggr for both nodes: msum = sum_k silu(y[j_k] + dist_k * wl)
    const float* yb = g_y + p*NNODE*FF + b*NAT*FF;
    float wl = wl_row[t];
    float s0 = 0.f, s1 = 0.f;
    #pragma unroll 4
    for (int k = 0; k < KNN; k++) {
        s0 += siluf(yb[sj[k]*FF + t]     + sdist[k]*wl);
        s1 += siluf(yb[sj[KNN+k]*FF + t] + sdist[KNN+k]*wl);
    }
    shm0[t] = s0; shm1[t] = s1;

    // lin2 both nodes (shared weight loads)
    float a0, a1;
    gemm128x2(W2, shm0, shm1, red, t, &a0, &a1);
    float bg = b2[t];
    float hn0 = g_h[n0*FF + t]     + siluf(a0 + bg);
    float hn1 = g_h[(n0+1)*FF + t] + siluf(a1 + bg);
    g_h[n0*FF + t] = hn0;
    g_h[(n0+1)*FF + t] = hn1;

    // per-node action dots (w_e = tanh(de_i + de_j) downstream)
    if (awe) {
        float ae = awe[t], ap = awp[t];
        float re0 = hn0*ae, rp0 = hn0*ap, re1 = hn1*ae, rp1 = hn1*ap;
        #pragma unroll
        for (int o = 16; o; o >>= 1) {
            re0 += __shfl_xor_sync(0xffffffffu, re0, o);
            rp0 += __shfl_xor_sync(0xffffffffu, rp0, o);
            re1 += __shfl_xor_sync(0xffffffffu, re1, o);
            rp1 += __shfl_xor_sync(0xffffffffu, rp1, o);
        }
        int w = t >> 5;
        if ((t & 31) == 0) { swe[w] = re0; swp[w] = rp0; swe[4+w] = re1; swp[4+w] = rp1; }
        __syncthreads();
        if (t == 0) {
            g_de[n0]   = swe[0]+swe[1]+swe[2]+swe[3];
            g_dp[n0]   = swp[0]+swp[1]+swp[2]+swp[3];
            g_de[n0+1] = swe[4]+swe[5]+swe[6]+swe[7];
            g_dp[n0+1] = swp[4]+swp[5]+swp[6]+swp[7];
        }
    }

    // lin1 of next layer
    if (W1n) {
        shh0[t] = hn0; shh1[t] = hn1;
        float y0, y1;
        gemm128x2(W1n, shh0, shh1, red, t, &y0, &y1);
        float bg1 = b1n[t];
        g_y[(p^1)*NNODE*FF + n0*FF + t]     = y0 + bg1;
        g_y[(p^1)*NNODE*FF + (n0+1)*FF + t] = y1 + bg1;
    }
}

// ---------------- edge weights + strain/tri + x_cart (geometry on the fly) ----------------
__global__ void __launch_bounds__(128) k_edgew()
{
    int node = blockIdx.x;
    int b = node >> 8;
    int t = threadIdx.x;
    int lane = t & 31;

    __shared__ float sh_we[KNN], sh_wp[KNN];
    __shared__ float su[KNN*3], sv[KNN*3];
    __shared__ float scell[9];
    __shared__ float snx[3];
    __shared__ float sT[6];

    if (t >= 32 && t < 41) scell[t-32] = g_cell[b*9 + (t-32)];
    if (t >= 64 && t < 67) snx[t-64] = g_x[node*3 + (t-64)];
    if (t < 6) sT[t] = 0.f;
    __syncthreads();

    // per-edge: vec/u on the fly (same expression as old k_edges) + tanh weights
    if (t < KNN) {
        int j = g_idx[node*KNN + t];
        const float* xb = g_x + b*NAT*3;
        float f0 = xb[j*3+0] - snx[0]; f0 -= rintf(f0);
        float f1 = xb[j*3+1] - snx[1]; f1 -= rintf(f1);
        float f2 = xb[j*3+2] - snx[2]; f2 -= rintf(f2);
        float v0 = f0*scell[0] + f1*scell[3] + f2*scell[6];
        float v1 = f0*scell[1] + f1*scell[4] + f2*scell[7];
        float v2 = f0*scell[2] + f1*scell[5] + f2*scell[8];
        float dd = sqrtf(v0*v0 + v1*v1 + v2*v2);
        float inv = 1.f / (dd + 1e-12f);
        sv[t*3+0] = v0; sv[t*3+1] = v1; sv[t*3+2] = v2;
        su[t*3+0] = v0*inv; su[t*3+1] = v1*inv; su[t*3+2] = v2*inv;
        sh_we[t] = tanhfast(g_de[node] + g_de[b*NAT + j]);
        sh_wp[t] = tanhfast(g_dp[node] + g_dp[b*NAT + j]);
    }
    __syncthreads();

    // strain partial (symmetric 6) and x_cart
    if (t < 6) {
        int c = c_pc[t], d = c_pd[t];
        float s = 0.f;
        #pragma unroll
        for (int k = 0; k < KNN; k++) s += sh_we[k] * su[k*3+c] * su[k*3+d];
        atomicAdd(&g_strain[b*6 + t], s);
    } else if (t >= 16 && t < 19) {
        int c = t - 16;
        float s = 0.f;
        #pragma unroll
        for (int k = 0; k < KNN; k++) s += sh_wp[k] * sv[k*3+c];
        g_xcart[node*3 + c] = EPSC * s;
    }

    // tri partial: 2 * sum over j<k pairs (packed mask)
    float T0=0.f,T1=0.f,T2=0.f,T3=0.f,T4=0.f,T5=0.f;
    const unsigned char* mp = g_maskp + node*NPAIR;
    for (int q = t; q < NPAIR; q += 128) {
        if (!mp[q]) continue;
        uchar2 pr = g_pairs[q];
        float wjk = sh_we[pr.x] * sh_we[pr.y];
        const float* a = su + pr.x*3;
        const float* c = su + pr.y*3;
        float c0 = a[1]*c[2] - a[2]*c[1];
        float c1 = a[2]*c[0] - a[0]*c[2];
        float c2 = a[0]*c[1] - a[1]*c[0];
        T0 += wjk*c0*c0; T1 += wjk*c0*c1; T2 += wjk*c0*c2;
        T3 += wjk*c1*c1; T4 += wjk*c1*c2; T5 += wjk*c2*c2;
    }
    #pragma unroll
    for (int o = 16; o; o >>= 1) {
        T0 += __shfl_xor_sync(0xffffffffu, T0, o);
        T1 += __shfl_xor_sync(0xffffffffu, T1, o);
        T2 += __shfl_xor_sync(0xffffffffu, T2, o);
        T3 += __shfl_xor_sync(0xffffffffu, T3, o);
        T4 += __shfl_xor_sync(0xffffffffu, T4, o);
        T5 += __shfl_xor_sync(0xffffffffu, T5, o);
    }
    if (lane == 0) {
        atomicAdd(&sT[0], 2.f*T0); atomicAdd(&sT[1], 2.f*T1); atomicAdd(&sT[2], 2.f*T2);
        atomicAdd(&sT[3], 2.f*T3); atomicAdd(&sT[4], 2.f*T4); atomicAdd(&sT[5], 2.f*T5);
    }
    __syncthreads();
    if (t < 6) atomicAdd(&g_tri[b*6 + t], sT[t]);
}

// ---------------- fused action + position update (one block per batch, 256 threads) --------
__global__ void __launch_bounds__(256) k_acpos(int is_last, float* __restrict__ out)
{
    int b = blockIdx.x;
    int t = threadIdx.x;
    __shared__ float s_iv[9];

    if (t == 0) {
        float s6[6], t6[6];
        #pragma unroll
        for (int i = 0; i < 6; i++) {
            s6[i] = g_strain[b*6+i]; t6[i] = g_tri[b*6+i];
            g_strain[b*6+i] = 0.f;   g_tri[b*6+i] = 0.f;
        }
        const float NK  = (float)(NAT*KNN);
        const float NKK = (float)(NAT*KNN*KNN);
        float P[9];
        P[0] = s6[0]/NK + t6[0]/NKK;
        P[1] = s6[1]/NK + t6[1]/NKK; P[3] = P[1];
        P[2] = s6[2]/NK + t6[2]/NKK; P[6] = P[2];
        P[4] = s6[3]/NK + t6[3]/NKK;
        P[5] = s6[4]/NK + t6[4]/NKK; P[7] = P[5];
        P[8] = s6[5]/NK + t6[5]/NKK;
        float A[9];
        #pragma unroll
        for (int i = 0; i < 9; i++) A[i] = EPSC*P[i] + ((i % 4 == 0) ? 1.f : 0.f);
        float R[9], C[9], Rn[9];
        #pragma unroll
        for (int i = 0; i < 9; i++) { R[i] = g_rho[b*9+i]; C[i] = g_cell[b*9+i]; }
        #pragma unroll
        for (int i = 0; i < 3; i++)
            #pragma unroll
            for (int k = 0; k < 3; k++)
                Rn[i*3+k] = A[i*3+0]*R[0+k] + A[i*3+1]*R[3+k] + A[i*3+2]*R[6+k];
        float det = C[0]*(C[4]*C[8]-C[5]*C[7]) - C[1]*(C[3]*C[8]-C[5]*C[6]) + C[2]*(C[3]*C[7]-C[4]*C[6]);
        float id = 1.f/det;
        s_iv[0]=(C[4]*C[8]-C[5]*C[7])*id;
        s_iv[1]=(C[2]*C[7]-C[1]*C[8])*id;
        s_iv[2]=(C[1]*C[5]-C[2]*C[4])*id;
        s_iv[3]=(C[5]*C[6]-C[3]*C[8])*id;
        s_iv[4]=(C[0]*C[8]-C[2]*C[6])*id;
        s_iv[5]=(C[2]*C[3]-C[0]*C[5])*id;
        s_iv[6]=(C[3]*C[7]-C[4]*C[6])*id;
        s_iv[7]=(C[1]*C[6]-C[0]*C[7])*id;
        s_iv[8]=(C[0]*C[4]-C[1]*C[3])*id;
        #pragma unroll
        for (int i = 0; i < 9; i++) {
            g_rho[b*9+i] = Rn[i];
            g_cell[b*9+i] = Rn[i];   // geo_cell = rho_prime (cell0 = I)
        }
        if (is_last) {
            #pragma unroll
            for (int i = 0; i < 9; i++) out[NNODE*3 + b*9 + i] = Rn[i];
        }
    }
    __syncthreads();

    int node = b*NAT + t;
    float xc0 = g_xcart[node*3+0];
    float xc1 = g_xcart[node*3+1];
    float xc2 = g_xcart[node*3+2];
    float xf0 = xc0*s_iv[0] + xc1*s_iv[3] + xc2*s_iv[6];
    float xf1 = xc0*s_iv[1] + xc1*s_iv[4] + xc2*s_iv[7];
    float xf2 = xc0*s_iv[2] + xc1*s_iv[5] + xc2*s_iv[8];
    g_x[node*3+0] += xf0;
    g_x[node*3+1] += xf1;
    g_x[node*3+2] += xf2;
    out[node*3+0] += xc0;
    out[node*3+1] += xc1;
    out[node*3+2] += xc2;
}

// ---------------- launch ----------------
extern "C" void kernel_launch(void* const* d_in, const int* in_sizes, int n_in,
                              void* d_out, int out_size) {
    const float* x_in = (const float*)d_in[1];
    const int*   z    = (const int*)  d_in[2];
    const float* emb  = (const float*)d_in[4];
    const float* mW1  = (const float*)d_in[5];
    const float* mb1  = (const float*)d_in[6];
    const float* mW2  = (const float*)d_in[7];
    const float* mb2  = (const float*)d_in[8];
    const float* uW1  = (const float*)d_in[9];
    const float* ub1  = (const float*)d_in[10];
    const float* uW2  = (const float*)d_in[11];
    const float* ub2  = (const float*)d_in[12];
    const float* awe  = (const float*)d_in[13];
    const float* awp  = (const float*)d_in[14];
    float* out = (float*)d_out;

    const int SZ1 = (FF+1)*FF;

    k_init  <<<48, 256>>>(x_in, out);
    k_knnGeo<<<NNODE, 256>>>();

    k_lin1n<<<NNODE/2, 128>>>(mW1, mb1, emb, z);
    int p = 0;
    for (int l = 0; l < LL; l++) {
        const float* W1n = (l < 3) ? (mW1 + (l+1)*SZ1) : uW1;
        const float* b1n = (l < 3) ? (mb1 + (l+1)*FF)  : ub1;
        k_fusedL<<<NNODE/2, 128>>>(mW1 + l*SZ1 + FF*FF, mW2 + l*FF*FF, mb2 + l*FF,
                                   W1n, b1n, (const float*)0, (const float*)0, p);
        p ^= 1;
    }
    for (int l = 0; l < LL; l++) {
        const float* W1n = (l < 3) ? (uW1 + (l+1)*SZ1) : (const float*)0;
        const float* b1n = (l < 3) ? (ub1 + (l+1)*FF)  : (const float*)0;
        k_fusedL<<<NNODE/2, 128>>>(uW1 + l*SZ1 + FF*FF, uW2 + l*FF*FF, ub2 + l*FF,
                                   W1n, b1n, awe + l*FF, awp + l*FF, p);
        p ^= 1;
        k_edgew<<<NNODE, 128>>>();
        k_acpos<<<BB, 256>>>(l == LL-1 ? 1 : 0, out);
    }
}